// round 1
// baseline (speedup 1.0000x reference)
#include <cuda_runtime.h>
#include <math_constants.h>

// erosion_and_dilation: fused 3x3 max (dilate) + 3x3 min (erode), fp32,
// shape (8,32,512,512) NCHW, border = valid-only (pad with +/-inf).
// Output: [dilated (67M floats) | eroded (67M floats)].
//
// One pass over DRAM: each thread owns a float4 column group (128 thr * 4 =
// 512 cols = full row width) and walks ROWS_PER_BLOCK rows with a 3-row
// rolling register window of horizontally-reduced min/max values.

#define W 512
#define H 512
#define ROWS_PER_BLOCK 64
#define THREADS 128  // * 4 cols = 512 = W

__global__ __launch_bounds__(THREADS)
void erode_dilate_kernel(const float* __restrict__ in,
                         float* __restrict__ dil,
                         float* __restrict__ ero)
{
    const int img  = blockIdx.y;                  // which 512x512 image
    const int r0   = blockIdx.x * ROWS_PER_BLOCK; // first output row
    const int x4   = threadIdx.x * 4;             // first column of this thread

    const float* base  = in  + (size_t)img * (H * W);
    float*       dbase = dil + (size_t)img * (H * W);
    float*       ebase = ero + (size_t)img * (H * W);

    const bool has_left  = (x4 > 0);
    const bool has_right = (x4 + 4 < W);

    // Rolling horizontal reductions for rows r-1, r, r+1
    float4 hmin_prev, hmin_cur, hmin_next;
    float4 hmax_prev, hmax_cur, hmax_next;

    // Load + horizontally reduce one row (row index must be in [0,H))
    auto load_row = [&](int r, float4& hmn, float4& hmx) {
        const float* rowp = base + (size_t)r * W;
        float4 v = *reinterpret_cast<const float4*>(rowp + x4);
        float lft = has_left  ? __ldg(rowp + x4 - 1) : 0.0f;
        float rgt = has_right ? __ldg(rowp + x4 + 4) : 0.0f;
        float lmin = has_left  ? lft :  CUDART_INF_F;
        float lmax = has_left  ? lft : -CUDART_INF_F;
        float rmin = has_right ? rgt :  CUDART_INF_F;
        float rmax = has_right ? rgt : -CUDART_INF_F;

        hmn.x = fminf(lmin, fminf(v.x, v.y));
        hmn.y = fminf(v.x, fminf(v.y, v.z));
        hmn.z = fminf(v.y, fminf(v.z, v.w));
        hmn.w = fminf(v.z, fminf(v.w, rmin));

        hmx.x = fmaxf(lmax, fmaxf(v.x, v.y));
        hmx.y = fmaxf(v.x, fmaxf(v.y, v.z));
        hmx.z = fmaxf(v.y, fmaxf(v.z, v.w));
        hmx.w = fmaxf(v.z, fmaxf(v.w, rmax));
    };

    const float4 INF4  = make_float4( CUDART_INF_F,  CUDART_INF_F,  CUDART_INF_F,  CUDART_INF_F);
    const float4 NINF4 = make_float4(-CUDART_INF_F, -CUDART_INF_F, -CUDART_INF_F, -CUDART_INF_F);

    // Prime the window: rows r0-1 and r0
    if (r0 - 1 >= 0) load_row(r0 - 1, hmin_prev, hmax_prev);
    else             { hmin_prev = INF4; hmax_prev = NINF4; }
    load_row(r0, hmin_cur, hmax_cur);

    #pragma unroll 4
    for (int r = r0; r < r0 + ROWS_PER_BLOCK; ++r) {
        if (r + 1 < H) load_row(r + 1, hmin_next, hmax_next);
        else           { hmin_next = INF4; hmax_next = NINF4; }

        float4 omin, omax;
        omin.x = fminf(hmin_prev.x, fminf(hmin_cur.x, hmin_next.x));
        omin.y = fminf(hmin_prev.y, fminf(hmin_cur.y, hmin_next.y));
        omin.z = fminf(hmin_prev.z, fminf(hmin_cur.z, hmin_next.z));
        omin.w = fminf(hmin_prev.w, fminf(hmin_cur.w, hmin_next.w));

        omax.x = fmaxf(hmax_prev.x, fmaxf(hmax_cur.x, hmax_next.x));
        omax.y = fmaxf(hmax_prev.y, fmaxf(hmax_cur.y, hmax_next.y));
        omax.z = fmaxf(hmax_prev.z, fmaxf(hmax_cur.z, hmax_next.z));
        omax.w = fmaxf(hmax_prev.w, fmaxf(hmax_cur.w, hmax_next.w));

        *reinterpret_cast<float4*>(dbase + (size_t)r * W + x4) = omax;
        *reinterpret_cast<float4*>(ebase + (size_t)r * W + x4) = omin;

        hmin_prev = hmin_cur;  hmin_cur = hmin_next;
        hmax_prev = hmax_cur;  hmax_cur = hmax_next;
    }
}

extern "C" void kernel_launch(void* const* d_in, const int* in_sizes, int n_in,
                              void* d_out, int out_size)
{
    const float* x = (const float*)d_in[0];
    const int n = in_sizes[0];              // 8*32*512*512 = 67108864
    const int nimg = n / (H * W);           // 256 images

    float* dil = (float*)d_out;             // dilated first
    float* ero = (float*)d_out + n;         // then eroded

    dim3 grid(H / ROWS_PER_BLOCK, nimg);    // (8, 256)
    erode_dilate_kernel<<<grid, THREADS>>>(x, dil, ero);
}

// round 2
// speedup vs baseline: 1.0482x; 1.0482x over previous
#include <cuda_runtime.h>
#include <math_constants.h>

// Fused 3x3 dilate (max) + erode (min), fp32, (8,32,512,512) NCHW.
// Border: reduce over valid pixels only (== +/-inf padding).
// Output layout: [dilated | eroded], each 67108864 floats.
//
// R2: pipelined rolling-window kernel.
//  - 128 threads * float4 = 512 cols = one full row per block-row-walk.
//  - ROWS_PER_BLOCK=32 (grid 16x256) for occupancy / wave balance.
//  - depth-2 software pipeline: fetch raw row r+2 while reducing row r+1
//    and storing row r -> batched independent LDGs per unrolled iter.
//  - horizontal halos via warp shuffle; only warp-edge lanes issue a
//    predicated scalar __ldg. Missing image-edge neighbor is replaced by
//    replicating the adjacent element (neutral for both min and max).

#define W 512
#define H 512
#define ROWS_PER_BLOCK 32
#define THREADS 128

struct Raw {
    float4 v;
    float lv, rv;   // warp-edge halo scalars (only meaningful on lanes 0/31)
};

__device__ __forceinline__ Raw fetch_row(const float* __restrict__ rowp,
                                         int x4, int lane)
{
    Raw f;
    f.v = *reinterpret_cast<const float4*>(rowp + x4);
    f.lv = 0.0f;
    f.rv = 0.0f;
    if (lane == 0  && x4 > 0)     f.lv = __ldg(rowp + x4 - 1);
    if (lane == 31 && x4 + 4 < W) f.rv = __ldg(rowp + x4 + 4);
    return f;
}

__device__ __forceinline__ void hreduce(const Raw& f, int x4, int lane,
                                        float4& hmn, float4& hmx)
{
    // neighbor left of v.x / right of v.w
    float l = __shfl_up_sync(0xffffffffu, f.v.w, 1);
    if (lane == 0)  l = (x4 > 0)     ? f.lv : f.v.x;   // replicate: neutral
    float r = __shfl_down_sync(0xffffffffu, f.v.x, 1);
    if (lane == 31) r = (x4 + 4 < W) ? f.rv : f.v.w;

    hmn.x = fminf(l,     fminf(f.v.x, f.v.y));
    hmn.y = fminf(f.v.x, fminf(f.v.y, f.v.z));
    hmn.z = fminf(f.v.y, fminf(f.v.z, f.v.w));
    hmn.w = fminf(f.v.z, fminf(f.v.w, r));

    hmx.x = fmaxf(l,     fmaxf(f.v.x, f.v.y));
    hmx.y = fmaxf(f.v.x, fmaxf(f.v.y, f.v.z));
    hmx.z = fmaxf(f.v.y, fmaxf(f.v.z, f.v.w));
    hmx.w = fmaxf(f.v.z, fmaxf(f.v.w, r));
}

__global__ __launch_bounds__(THREADS)
void erode_dilate_kernel(const float* __restrict__ in,
                         float* __restrict__ dil,
                         float* __restrict__ ero)
{
    const int img  = blockIdx.y;
    const int r0   = blockIdx.x * ROWS_PER_BLOCK;
    const int lane = threadIdx.x & 31;
    const int x4   = threadIdx.x * 4;

    const float* base  = in  + (size_t)img * (H * W);
    float*       dbase = dil + (size_t)img * (H * W);
    float*       ebase = ero + (size_t)img * (H * W);

    const float4 INF4  = make_float4( CUDART_INF_F,  CUDART_INF_F,
                                      CUDART_INF_F,  CUDART_INF_F);
    const float4 NINF4 = make_float4(-CUDART_INF_F, -CUDART_INF_F,
                                     -CUDART_INF_F, -CUDART_INF_F);

    float4 hmnp, hmxp, hmnc, hmxc;

    // Prime: row r0-1 (or inf), row r0, and raw fetch of r0+1.
    if (r0 > 0) {
        Raw f = fetch_row(base + (size_t)(r0 - 1) * W, x4, lane);
        hreduce(f, x4, lane, hmnp, hmxp);
    } else {
        hmnp = INF4; hmxp = NINF4;
    }
    {
        Raw f = fetch_row(base + (size_t)r0 * W, x4, lane);
        hreduce(f, x4, lane, hmnc, hmxc);
    }
    Raw fn = fetch_row(base + (size_t)(r0 + 1) * W, x4, lane);  // r0+1 < H always

    #pragma unroll 4
    for (int r = r0; r < r0 + ROWS_PER_BLOCK; ++r) {
        // Fetch row r+2 (needed through r0+ROWS_PER_BLOCK; clamp at image end)
        Raw f2;
        const bool need2 = (r + 2 <= r0 + ROWS_PER_BLOCK) && (r + 2 < H);
        if (need2) f2 = fetch_row(base + (size_t)(r + 2) * W, x4, lane);

        float4 hmnn, hmxn;
        if (r + 1 < H) {
            hreduce(fn, x4, lane, hmnn, hmxn);
        } else {
            hmnn = INF4; hmxn = NINF4;
        }

        float4 omin, omax;
        omin.x = fminf(hmnp.x, fminf(hmnc.x, hmnn.x));
        omin.y = fminf(hmnp.y, fminf(hmnc.y, hmnn.y));
        omin.z = fminf(hmnp.z, fminf(hmnc.z, hmnn.z));
        omin.w = fminf(hmnp.w, fminf(hmnc.w, hmnn.w));

        omax.x = fmaxf(hmxp.x, fmaxf(hmxc.x, hmxn.x));
        omax.y = fmaxf(hmxp.y, fmaxf(hmxc.y, hmxn.y));
        omax.z = fmaxf(hmxp.z, fmaxf(hmxc.z, hmxn.z));
        omax.w = fmaxf(hmxp.w, fmaxf(hmxc.w, hmxn.w));

        *reinterpret_cast<float4*>(dbase + (size_t)r * W + x4) = omax;
        *reinterpret_cast<float4*>(ebase + (size_t)r * W + x4) = omin;

        fn = f2;
        hmnp = hmnc; hmxp = hmxc;
        hmnc = hmnn; hmxc = hmxn;
    }
}

extern "C" void kernel_launch(void* const* d_in, const int* in_sizes, int n_in,
                              void* d_out, int out_size)
{
    const float* x = (const float*)d_in[0];
    const int n = in_sizes[0];              // 67108864
    const int nimg = n / (H * W);           // 256

    float* dil = (float*)d_out;
    float* ero = (float*)d_out + n;

    dim3 grid(H / ROWS_PER_BLOCK, nimg);    // (16, 256)
    erode_dilate_kernel<<<grid, THREADS>>>(x, dil, ero);
}

// round 4
// speedup vs baseline: 1.0947x; 1.0443x over previous
#include <cuda_runtime.h>

// Fused 3x3 dilate (max) + erode (min), fp32, (8,32,512,512) NCHW.
// Border: reduce over valid pixels only. Output: [dilated | eroded].
//
// R4 (= R3 re-bench; previous round was an infra failure, kernel untested):
// vertical-first rolling window to halve register state.
//  - per thread: raw rows prev/cur (2 x float4) + 4 halo scalars.
//  - per output row: load raw next, vertical min/max (shared raw rows serve
//    both reductions), then horizontal 3-reduce via warp shuffles.
//  - all out-of-range neighbors handled by REPLICATION (idempotent for
//    min/max): no infinity constants, no extra predicate registers.
//  - __launch_bounds__(128, 11) caps regs (~46) for ~69% occupancy.
//  - streaming stores (st.global.cs): outputs are never re-read.

#define W 512
#define H 512
#define ROWS_PER_BLOCK 32
#define THREADS 128

__device__ __forceinline__ void stcs4(float* p, float4 v) {
    asm volatile("st.global.cs.v4.f32 [%0], {%1,%2,%3,%4};"
                 :: "l"(p), "f"(v.x), "f"(v.y), "f"(v.z), "f"(v.w) : "memory");
}

__device__ __forceinline__ void load_row(const float* __restrict__ rowp,
                                         int x4, int lane,
                                         float4& v, float& lv, float& rv)
{
    v = *reinterpret_cast<const float4*>(rowp + x4);
    // warp-edge halo scalars; replicate at image edge (neutral for min/max)
    lv = v.x;
    rv = v.w;
    if (lane == 0  && x4 > 0)     lv = __ldg(rowp + x4 - 1);
    if (lane == 31 && x4 + 4 < W) rv = __ldg(rowp + x4 + 4);
}

__global__ __launch_bounds__(THREADS, 11)
void erode_dilate_kernel(const float* __restrict__ in,
                         float* __restrict__ dil,
                         float* __restrict__ ero)
{
    const int img  = blockIdx.y;
    const int r0   = blockIdx.x * ROWS_PER_BLOCK;
    const int lane = threadIdx.x & 31;
    const int x4   = threadIdx.x * 4;

    const size_t ibase = (size_t)img * (H * W);
    const float* base  = in  + ibase;
    float*       dbase = dil + ibase;
    float*       ebase = ero + ibase;

    // Rolling raw rows r-1 (pv) and r (cv) + their halo scalars
    float4 pv, cv;
    float plv, prv, clv, crv;

    load_row(base + (size_t)r0 * W, x4, lane, cv, clv, crv);
    if (r0 > 0) {
        load_row(base + (size_t)(r0 - 1) * W, x4, lane, pv, plv, prv);
    } else {
        pv = cv; plv = clv; prv = crv;   // replicate top row (neutral)
    }

    #pragma unroll 8
    for (int i = 0; i < ROWS_PER_BLOCK; ++i) {
        const int r = r0 + i;

        // raw row r+1 (replicate cur at bottom edge)
        float4 nv; float nlv, nrv;
        if (r + 1 < H) {
            load_row(base + (size_t)(r + 1) * W, x4, lane, nv, nlv, nrv);
        } else {
            nv = cv; nlv = clv; nrv = crv;
        }

        // ---- min path ----
        float4 vmn;
        vmn.x = fminf(pv.x, fminf(cv.x, nv.x));
        vmn.y = fminf(pv.y, fminf(cv.y, nv.y));
        vmn.z = fminf(pv.z, fminf(cv.z, nv.z));
        vmn.w = fminf(pv.w, fminf(cv.w, nv.w));
        const float vmn_l = fminf(plv, fminf(clv, nlv));
        const float vmn_r = fminf(prv, fminf(crv, nrv));

        float lmn = __shfl_up_sync(0xffffffffu, vmn.w, 1);
        if (lane == 0)  lmn = vmn_l;
        float rmn = __shfl_down_sync(0xffffffffu, vmn.x, 1);
        if (lane == 31) rmn = vmn_r;

        float4 omin;
        omin.x = fminf(lmn,   fminf(vmn.x, vmn.y));
        omin.y = fminf(vmn.x, fminf(vmn.y, vmn.z));
        omin.z = fminf(vmn.y, fminf(vmn.z, vmn.w));
        omin.w = fminf(vmn.z, fminf(vmn.w, rmn));
        stcs4(ebase + (size_t)r * W + x4, omin);

        // ---- max path ----
        float4 vmx;
        vmx.x = fmaxf(pv.x, fmaxf(cv.x, nv.x));
        vmx.y = fmaxf(pv.y, fmaxf(cv.y, nv.y));
        vmx.z = fmaxf(pv.z, fmaxf(cv.z, nv.z));
        vmx.w = fmaxf(pv.w, fmaxf(cv.w, nv.w));
        const float vmx_l = fmaxf(plv, fmaxf(clv, nlv));
        const float vmx_r = fmaxf(prv, fmaxf(crv, nrv));

        float lmx = __shfl_up_sync(0xffffffffu, vmx.w, 1);
        if (lane == 0)  lmx = vmx_l;
        float rmx = __shfl_down_sync(0xffffffffu, vmx.x, 1);
        if (lane == 31) rmx = vmx_r;

        float4 omax;
        omax.x = fmaxf(lmx,   fmaxf(vmx.x, vmx.y));
        omax.y = fmaxf(vmx.x, fmaxf(vmx.y, vmx.z));
        omax.z = fmaxf(vmx.y, fmaxf(vmx.z, vmx.w));
        omax.w = fmaxf(vmx.z, fmaxf(vmx.w, rmx));
        stcs4(dbase + (size_t)r * W + x4, omax);

        pv = cv; cv = nv;
        plv = clv; clv = nlv;
        prv = crv; crv = nrv;
    }
}

extern "C" void kernel_launch(void* const* d_in, const int* in_sizes, int n_in,
                              void* d_out, int out_size)
{
    const float* x = (const float*)d_in[0];
    const int n = in_sizes[0];              // 67108864
    const int nimg = n / (H * W);           // 256

    float* dil = (float*)d_out;
    float* ero = (float*)d_out + n;

    dim3 grid(H / ROWS_PER_BLOCK, nimg);    // (16, 256)
    erode_dilate_kernel<<<grid, THREADS>>>(x, dil, ero);
}

// round 5
// speedup vs baseline: 1.2949x; 1.1829x over previous
#include <cuda_runtime.h>
#include <cstdint>

// Fused 3x3 dilate (max) + erode (min), fp32, (8,32,512,512) NCHW.
// Border: reduce over valid pixels only (replication == +/-inf pad).
// Output: [dilated | eroded], each 67108864 floats.
//
// R5: bulk-async (UBLKCP) staging to decouple MLP from registers.
//  - Each block handles 8 output rows of one image. Its 10 input rows
//    (8 + 2 halo) are CONTIGUOUS in gmem -> ONE cp.async.bulk of 20KB
//    into static smem, completion via mbarrier.
//  - ~11 blocks/SM co-resident (20.5KB smem each) => ~220KB of copy
//    traffic in flight per SM: DRAM latency fully covered without any
//    register pressure.
//  - Compute: rolling 3-row window read from smem (each row read once),
//    true left/right neighbors read directly from smem (no shuffles).
//    Edge handling by replication (neutral for min/max).
//  - Streaming float4 stores (outputs never re-read).

#define W 512
#define H 512
#define ROWS_OUT 8
#define ROWS_IN  10                     // ROWS_OUT + 2 halo rows
#define THREADS 128                     // * 4 cols = full 512-wide row
#define CHUNKS_PER_IMG (H / ROWS_OUT)   // 64
#define STAGE_BYTES (ROWS_IN * W * 4)   // 20480

__device__ __forceinline__ void stcs4(float* p, float4 v) {
    asm volatile("st.global.cs.v4.f32 [%0], {%1,%2,%3,%4};"
                 :: "l"(p), "f"(v.x), "f"(v.y), "f"(v.z), "f"(v.w) : "memory");
}

__device__ __forceinline__ void mbar_wait_parity0(uint32_t mbar) {
    asm volatile(
        "{\n\t"
        ".reg .pred P;\n\t"
        "WAIT_%=:\n\t"
        "mbarrier.try_wait.parity.shared.b64 P, [%0], 0, 10000000;\n\t"
        "@P bra.uni DONE_%=;\n\t"
        "bra.uni WAIT_%=;\n\t"
        "DONE_%=:\n\t"
        "}"
        :: "r"(mbar) : "memory");
}

__global__ __launch_bounds__(THREADS)
void erode_dilate_kernel(const float* __restrict__ in,
                         float* __restrict__ dil,
                         float* __restrict__ ero)
{
    __shared__ __align__(128) float buf[ROWS_IN * W];
    __shared__ uint64_t mbar;

    const int bid = blockIdx.x;
    const int img = bid >> 6;            // / CHUNKS_PER_IMG
    const int chk = bid & 63;
    const int r0  = chk * ROWS_OUT;

    // input row window [y0, y0+ROWS_IN) clamped inside the image
    int y0 = r0 - 1;
    if (y0 < 0) y0 = 0;
    if (y0 > H - ROWS_IN) y0 = H - ROWS_IN;

    const int tid = threadIdx.x;
    const int x4  = tid * 4;
    const size_t ibase = (size_t)img * (H * W);
    const float* src = in + ibase + (size_t)y0 * W;

    const uint32_t s_data = (uint32_t)__cvta_generic_to_shared(buf);
    const uint32_t s_mbar = (uint32_t)__cvta_generic_to_shared(&mbar);

    if (tid == 0) {
        asm volatile("mbarrier.init.shared.b64 [%0], 1;" :: "r"(s_mbar));
    }
    __syncthreads();
    if (tid == 0) {
        asm volatile("mbarrier.arrive.expect_tx.shared.b64 _, [%0], %1;"
                     :: "r"(s_mbar), "r"((uint32_t)STAGE_BYTES));
        asm volatile(
            "cp.async.bulk.shared::cluster.global.mbarrier::complete_tx::bytes "
            "[%0], [%1], %2, [%3];"
            :: "r"(s_data), "l"(src), "r"((uint32_t)STAGE_BYTES), "r"(s_mbar)
            : "memory");
    }
    mbar_wait_parity0(s_mbar);

    // read one staged row: float4 + true left/right neighbor scalars
    auto read_row = [&](int si, float4& v, float& lv, float& rv) {
        const float* rp = buf + si * W;
        v  = *reinterpret_cast<const float4*>(rp + x4);
        lv = (x4 > 0)     ? rp[x4 - 1] : v.x;   // replicate at image edge
        rv = (x4 + 4 < W) ? rp[x4 + 4] : v.w;
    };

    float4 pv, cv, nv;
    float plv, prv, clv, crv, nlv, nrv;

    int sp = r0 - 1 - y0; if (sp < 0) sp = 0;       // replicate top row
    read_row(sp,      pv, plv, prv);
    read_row(r0 - y0, cv, clv, crv);

    float* drow = dil + ibase + (size_t)r0 * W + x4;
    float* erow = ero + ibase + (size_t)r0 * W + x4;

    #pragma unroll
    for (int i = 0; i < ROWS_OUT; ++i) {
        int sn = r0 + i + 1 - y0;
        if (sn > ROWS_IN - 1) sn = ROWS_IN - 1;     // replicate bottom row
        read_row(sn, nv, nlv, nrv);

        // vertical 3-reduce (raw rows feed BOTH min and max)
        float4 vmn, vmx;
        vmn.x = fminf(pv.x, fminf(cv.x, nv.x));
        vmn.y = fminf(pv.y, fminf(cv.y, nv.y));
        vmn.z = fminf(pv.z, fminf(cv.z, nv.z));
        vmn.w = fminf(pv.w, fminf(cv.w, nv.w));
        vmx.x = fmaxf(pv.x, fmaxf(cv.x, nv.x));
        vmx.y = fmaxf(pv.y, fmaxf(cv.y, nv.y));
        vmx.z = fmaxf(pv.z, fmaxf(cv.z, nv.z));
        vmx.w = fmaxf(pv.w, fmaxf(cv.w, nv.w));

        const float vl_mn = fminf(plv, fminf(clv, nlv));
        const float vl_mx = fmaxf(plv, fmaxf(clv, nlv));
        const float vr_mn = fminf(prv, fminf(crv, nrv));
        const float vr_mx = fmaxf(prv, fmaxf(crv, nrv));

        // horizontal 3-reduce
        float4 omin, omax;
        omin.x = fminf(vl_mn, fminf(vmn.x, vmn.y));
        omin.y = fminf(vmn.x, fminf(vmn.y, vmn.z));
        omin.z = fminf(vmn.y, fminf(vmn.z, vmn.w));
        omin.w = fminf(vmn.z, fminf(vmn.w, vr_mn));

        omax.x = fmaxf(vl_mx, fmaxf(vmx.x, vmx.y));
        omax.y = fmaxf(vmx.x, fmaxf(vmx.y, vmx.z));
        omax.z = fmaxf(vmx.y, fmaxf(vmx.z, vmx.w));
        omax.w = fmaxf(vmx.z, fmaxf(vmx.w, vr_mx));

        stcs4(drow, omax);
        stcs4(erow, omin);
        drow += W;
        erow += W;

        pv = cv; cv = nv;
        plv = clv; clv = nlv;
        prv = crv; crv = nrv;
    }
}

extern "C" void kernel_launch(void* const* d_in, const int* in_sizes, int n_in,
                              void* d_out, int out_size)
{
    const float* x = (const float*)d_in[0];
    const int n = in_sizes[0];                  // 67108864
    const int nimg = n / (H * W);               // 256

    float* dil = (float*)d_out;
    float* ero = (float*)d_out + n;

    const int nblocks = nimg * CHUNKS_PER_IMG;  // 16384
    erode_dilate_kernel<<<nblocks, THREADS>>>(x, dil, ero);
}

// round 6
// speedup vs baseline: 1.2969x; 1.0015x over previous
#include <cuda_runtime.h>
#include <cstdint>

// Fused 3x3 dilate (max) + erode (min), fp32, (8,32,512,512) NCHW.
// Border: reduce over valid pixels only (replication == +/-inf pad).
// Output: [dilated | eroded], each 67108864 floats.
//
// R6: double-buffered bulk-async pipeline.
//  - Each block handles TWO 8-row chunks (16 output rows). Both 20KB
//    cp.async.bulk copies are issued at block start into separate smem
//    buffers with separate mbarriers: chunk B's DRAM latency is hidden
//    behind chunk A's compute.
//  - 41KB smem/block -> 5 blocks/SM, 200KB copy traffic in flight per SM
//    at block start; grid 8192.
//  - Compute: rolling 3-row register window over smem rows; true left/
//    right neighbors read directly from smem; edge replication (neutral
//    for min/max). Streaming float4 stores.

#define W 512
#define H 512
#define ROWS_OUT 8
#define ROWS_IN  10                     // ROWS_OUT + 2 halo
#define THREADS 128
#define CPB 2                           // chunks per block
#define STAGE_BYTES (ROWS_IN * W * 4)   // 20480

__device__ __forceinline__ void stcs4(float* p, float4 v) {
    asm volatile("st.global.cs.v4.f32 [%0], {%1,%2,%3,%4};"
                 :: "l"(p), "f"(v.x), "f"(v.y), "f"(v.z), "f"(v.w) : "memory");
}

__device__ __forceinline__ void mbar_wait_parity0(uint32_t mbar) {
    asm volatile(
        "{\n\t"
        ".reg .pred P;\n\t"
        "WAIT_%=:\n\t"
        "mbarrier.try_wait.parity.shared.b64 P, [%0], 0, 10000000;\n\t"
        "@P bra.uni DONE_%=;\n\t"
        "bra.uni WAIT_%=;\n\t"
        "DONE_%=:\n\t"
        "}"
        :: "r"(mbar) : "memory");
}

__device__ __forceinline__ void bulk_copy(uint32_t s_data, const float* src,
                                          uint32_t s_mbar) {
    asm volatile("mbarrier.arrive.expect_tx.shared.b64 _, [%0], %1;"
                 :: "r"(s_mbar), "r"((uint32_t)STAGE_BYTES));
    asm volatile(
        "cp.async.bulk.shared::cluster.global.mbarrier::complete_tx::bytes "
        "[%0], [%1], %2, [%3];"
        :: "r"(s_data), "l"(src), "r"((uint32_t)STAGE_BYTES), "r"(s_mbar)
        : "memory");
}

__device__ __forceinline__ void compute_chunk(const float* __restrict__ buf,
                                              int r0, int y0, int x4,
                                              float* __restrict__ dbase,
                                              float* __restrict__ ebase)
{
    auto read_row = [&](int si, float4& v, float& lv, float& rv) {
        const float* rp = buf + si * W;
        v  = *reinterpret_cast<const float4*>(rp + x4);
        lv = (x4 > 0)     ? rp[x4 - 1] : v.x;   // replicate at image edge
        rv = (x4 + 4 < W) ? rp[x4 + 4] : v.w;
    };

    float4 pv, cv, nv;
    float plv, prv, clv, crv, nlv, nrv;

    int sp = r0 - 1 - y0; if (sp < 0) sp = 0;       // replicate top row
    read_row(sp,      pv, plv, prv);
    read_row(r0 - y0, cv, clv, crv);

    float* drow = dbase + (size_t)r0 * W + x4;
    float* erow = ebase + (size_t)r0 * W + x4;

    #pragma unroll
    for (int i = 0; i < ROWS_OUT; ++i) {
        int sn = r0 + i + 1 - y0;
        if (sn > ROWS_IN - 1) sn = ROWS_IN - 1;     // replicate bottom row
        read_row(sn, nv, nlv, nrv);

        float4 vmn, vmx;
        vmn.x = fminf(pv.x, fminf(cv.x, nv.x));
        vmn.y = fminf(pv.y, fminf(cv.y, nv.y));
        vmn.z = fminf(pv.z, fminf(cv.z, nv.z));
        vmn.w = fminf(pv.w, fminf(cv.w, nv.w));
        vmx.x = fmaxf(pv.x, fmaxf(cv.x, nv.x));
        vmx.y = fmaxf(pv.y, fmaxf(cv.y, nv.y));
        vmx.z = fmaxf(pv.z, fmaxf(cv.z, nv.z));
        vmx.w = fmaxf(pv.w, fmaxf(cv.w, nv.w));

        const float vl_mn = fminf(plv, fminf(clv, nlv));
        const float vl_mx = fmaxf(plv, fmaxf(clv, nlv));
        const float vr_mn = fminf(prv, fminf(crv, nrv));
        const float vr_mx = fmaxf(prv, fmaxf(crv, nrv));

        float4 omin, omax;
        omin.x = fminf(vl_mn, fminf(vmn.x, vmn.y));
        omin.y = fminf(vmn.x, fminf(vmn.y, vmn.z));
        omin.z = fminf(vmn.y, fminf(vmn.z, vmn.w));
        omin.w = fminf(vmn.z, fminf(vmn.w, vr_mn));

        omax.x = fmaxf(vl_mx, fmaxf(vmx.x, vmx.y));
        omax.y = fmaxf(vmx.x, fmaxf(vmx.y, vmx.z));
        omax.z = fmaxf(vmx.y, fmaxf(vmx.z, vmx.w));
        omax.w = fmaxf(vmx.z, fmaxf(vmx.w, vr_mx));

        stcs4(drow, omax);
        stcs4(erow, omin);
        drow += W;
        erow += W;

        pv = cv; cv = nv;
        plv = clv; clv = nlv;
        prv = crv; crv = nrv;
    }
}

__global__ __launch_bounds__(THREADS)
void erode_dilate_kernel(const float* __restrict__ in,
                         float* __restrict__ dil,
                         float* __restrict__ ero)
{
    __shared__ __align__(128) float buf[CPB][ROWS_IN * W];
    __shared__ uint64_t mbar[CPB];

    const int bid = blockIdx.x;
    const int img = bid >> 5;            // / 32 block-pairs per image
    const int pr  = bid & 31;            // which pair of chunks
    const int r0a = pr * (ROWS_OUT * CPB);
    const int r0b = r0a + ROWS_OUT;

    // clamped input windows
    int y0a = r0a - 1;
    if (y0a < 0) y0a = 0;
    if (y0a > H - ROWS_IN) y0a = H - ROWS_IN;
    int y0b = r0b - 1;
    if (y0b > H - ROWS_IN) y0b = H - ROWS_IN;

    const int tid = threadIdx.x;
    const int x4  = tid * 4;
    const size_t ibase = (size_t)img * (H * W);
    const float* base  = in  + ibase;
    float*       dbase = dil + ibase;
    float*       ebase = ero + ibase;

    const uint32_t s_buf0 = (uint32_t)__cvta_generic_to_shared(&buf[0][0]);
    const uint32_t s_buf1 = (uint32_t)__cvta_generic_to_shared(&buf[1][0]);
    const uint32_t s_mb0  = (uint32_t)__cvta_generic_to_shared(&mbar[0]);
    const uint32_t s_mb1  = (uint32_t)__cvta_generic_to_shared(&mbar[1]);

    if (tid == 0) {
        asm volatile("mbarrier.init.shared.b64 [%0], 1;" :: "r"(s_mb0));
        asm volatile("mbarrier.init.shared.b64 [%0], 1;" :: "r"(s_mb1));
    }
    __syncthreads();
    if (tid == 0) {
        bulk_copy(s_buf0, base + (size_t)y0a * W, s_mb0);
        bulk_copy(s_buf1, base + (size_t)y0b * W, s_mb1);
    }

    mbar_wait_parity0(s_mb0);
    compute_chunk(&buf[0][0], r0a, y0a, x4, dbase, ebase);

    mbar_wait_parity0(s_mb1);
    compute_chunk(&buf[1][0], r0b, y0b, x4, dbase, ebase);
}

extern "C" void kernel_launch(void* const* d_in, const int* in_sizes, int n_in,
                              void* d_out, int out_size)
{
    const float* x = (const float*)d_in[0];
    const int n = in_sizes[0];                      // 67108864
    const int nimg = n / (H * W);                   // 256

    float* dil = (float*)d_out;
    float* ero = (float*)d_out + n;

    const int nblocks = nimg * (H / (ROWS_OUT * CPB));  // 8192
    erode_dilate_kernel<<<nblocks, THREADS>>>(x, dil, ero);
}